// round 1
// baseline (speedup 1.0000x reference)
#include <cuda_runtime.h>
#include <cstdint>
#include <math.h>

// Problem sizes (fixed by the dataset)
#define NE   32      // experts
#define HD   2048    // hidden
#define ID   1536    // intermediate
#define NTOK 1024    // tokens
#define TOPK 8
#define NP   (NTOK*TOPK)   // 8192 routed pairs

// GEMM tiling
#define BM   128
#define BK   32
#define LDK  (BK+4)        // 36-float smem row stride: conflict-free frag loads
#define TILE (128*LDK)     // one 128-row tile buffer (floats)
#define MAXMT 96           // sum ceil(cnt_e/BM) <= NP/BM + NE = 96
#define SMEMB (4*TILE*4)   // As[2] + Bs[2], bytes = 73728

// ---------------- device scratch (static: no allocations allowed) ----------
__device__ int   g_perm[NP];           // grouped order -> token id
__device__ float g_pw[NP];             // grouped order -> router weight
__device__ int   g_off[NE+1];          // expert segment offsets
__device__ int   g_mt_e[MAXMT];        // m-tile -> expert
__device__ int   g_mt_r[MAXMT];        // m-tile -> first row (grouped index)
__device__ int   g_nmt;                // number of m-tiles
__device__ float g_act[(size_t)NP*ID]; // 48 MB fused silu(gate)*up*w activations

// ---------------- helpers --------------------------------------------------
__device__ __forceinline__ float to_tf32(float x){
  uint32_t u; asm("cvt.rna.tf32.f32 %0, %1;" : "=r"(u) : "f"(x));
  return __uint_as_float(u);
}

__device__ __forceinline__ void mma_tf32(float d[4], const float a[4], const float b[2]){
  asm volatile(
    "mma.sync.aligned.m16n8k8.row.col.f32.tf32.tf32.f32 "
    "{%0,%1,%2,%3}, {%4,%5,%6,%7}, {%8,%9}, {%0,%1,%2,%3};\n"
    : "+f"(d[0]), "+f"(d[1]), "+f"(d[2]), "+f"(d[3])
    : "r"(__float_as_uint(a[0])), "r"(__float_as_uint(a[1])),
      "r"(__float_as_uint(a[2])), "r"(__float_as_uint(a[3])),
      "r"(__float_as_uint(b[0])), "r"(__float_as_uint(b[1])));
}

// ---------------- kernels --------------------------------------------------
__global__ void zero_out_kernel(float* __restrict__ out){
  int i = blockIdx.x*256 + threadIdx.x;
  if (i < NTOK*HD) out[i] = 0.f;
}

// Build per-expert segments + m-tile descriptors + scatter (token, weight)
__global__ void route_kernel(const int* __restrict__ idx, const float* __restrict__ w){
  __shared__ int cnt[NE];
  __shared__ int cur[NE];
  __shared__ int soff[NE+1];
  int tid = threadIdx.x;
  if (tid < NE) cnt[tid] = 0;
  __syncthreads();
  for (int i = tid; i < NP; i += blockDim.x) atomicAdd(&cnt[idx[i]], 1);
  __syncthreads();
  if (tid == 0){
    int s = 0, nm = 0;
    for (int e = 0; e < NE; e++){
      soff[e] = s;
      for (int j = 0; j < cnt[e]; j += BM){ g_mt_e[nm] = e; g_mt_r[nm] = s + j; nm++; }
      s += cnt[e];
    }
    soff[NE] = s;
    g_nmt = nm;
  }
  __syncthreads();
  if (tid <= NE) g_off[tid] = soff[tid];
  if (tid <  NE) cur[tid]  = soff[tid];
  __syncthreads();
  for (int i = tid; i < NP; i += blockDim.x){
    int e = idx[i];
    int p = atomicAdd(&cur[e], 1);
    g_perm[p] = i / TOPK;
    g_pw[p]   = w[i];
  }
}

// GEMM1: act[p, i0..i0+63] = w_p * silu(X_p . Wg_i) * (X_p . Wu_i)
// A: gathered token rows (BM x HD), B: 64 gate rows + 64 up rows of gate_up[e]
__global__ void gemm1_kernel(const float* __restrict__ X, const float* __restrict__ GU)
{
  int mt = blockIdx.x;
  if (mt >= g_nmt) return;
  const int e = g_mt_e[mt], row0 = g_mt_r[mt], pend = g_off[e+1];
  const int i0 = blockIdx.y * 64;
  extern __shared__ float sm[];
  float* As = sm;            // [2][128][LDK]
  float* Bs = sm + 2*TILE;   // [2][128][LDK] rows 0..63 gate, 64..127 up

  const int tid = threadIdx.x, lane = tid & 31, wid = tid >> 5;
  const int mw = wid >> 1, nw = wid & 1;      // 4 m-warps x 2 n-warps
  const int kq = tid & 7, rr = tid >> 3;      // loader: 8 lanes cover one 128B row-chunk

  const float* aptr[4];
  const float* bptr[4];
  {
    const float* gu_e = GU + (size_t)e * (2*ID) * HD;
    #pragma unroll
    for (int t = 0; t < 4; t++){
      int m = rr + t*32;
      int p = row0 + m;
      int pc = (p < pend) ? p : row0;                // clamp; epilogue guards
      aptr[t] = X + (size_t)g_perm[pc] * HD + kq*4;
      int grow = (m < 64) ? (i0 + m) : (ID + i0 + (m - 64));
      bptr[t] = gu_e + (size_t)grow * HD + kq*4;
    }
  }

  float accg[2][4][4], accu[2][4][4];
  #pragma unroll
  for (int a=0;a<2;a++)
    #pragma unroll
    for (int b=0;b<4;b++)
      #pragma unroll
      for (int q=0;q<4;q++){ accg[a][b][q]=0.f; accu[a][b][q]=0.f; }

  float4 ra[4], rb[4];
  #pragma unroll
  for (int t=0;t<4;t++){ ra[t] = *(const float4*)aptr[t]; rb[t] = *(const float4*)bptr[t]; }
  #pragma unroll
  for (int t=0;t<4;t++){
    float* da = As + (rr + t*32)*LDK + kq*4;
    da[0]=to_tf32(ra[t].x); da[1]=to_tf32(ra[t].y); da[2]=to_tf32(ra[t].z); da[3]=to_tf32(ra[t].w);
    float* db = Bs + (rr + t*32)*LDK + kq*4;
    db[0]=to_tf32(rb[t].x); db[1]=to_tf32(rb[t].y); db[2]=to_tf32(rb[t].z); db[3]=to_tf32(rb[t].w);
  }
  __syncthreads();

  const int NKT = HD / BK;   // 64
  for (int kt = 0; kt < NKT; kt++){
    const int cb = kt & 1;
    if (kt + 1 < NKT){
      const int ko = (kt+1)*BK;
      #pragma unroll
      for (int t=0;t<4;t++){ ra[t] = *(const float4*)(aptr[t]+ko); rb[t] = *(const float4*)(bptr[t]+ko); }
    }
    {
      const float* Ab = As + cb*TILE + (mw*32)*LDK;
      const float* Bb = Bs + cb*TILE + (nw*32)*LDK;
      const int g = lane >> 2, c = lane & 3;
      #pragma unroll
      for (int ks = 0; ks < 4; ks++){
        const int k0 = ks*8 + c;
        float a[2][4];
        #pragma unroll
        for (int mi=0;mi<2;mi++){
          const float* ap = Ab + (mi*16 + g)*LDK + k0;
          a[mi][0] = ap[0];       a[mi][2] = ap[4];
          a[mi][1] = ap[8*LDK];   a[mi][3] = ap[8*LDK+4];
        }
        #pragma unroll
        for (int ni=0;ni<4;ni++){
          const float* bp = Bb + (ni*8 + g)*LDK + k0;
          float bg[2] = { bp[0], bp[4] };
          float bu[2] = { bp[64*LDK], bp[64*LDK+4] };
          mma_tf32(accg[0][ni], a[0], bg);
          mma_tf32(accg[1][ni], a[1], bg);
          mma_tf32(accu[0][ni], a[0], bu);
          mma_tf32(accu[1][ni], a[1], bu);
        }
      }
    }
    if (kt + 1 < NKT){
      const int wb = 1 - cb;
      #pragma unroll
      for (int t=0;t<4;t++){
        float* da = As + wb*TILE + (rr + t*32)*LDK + kq*4;
        da[0]=to_tf32(ra[t].x); da[1]=to_tf32(ra[t].y); da[2]=to_tf32(ra[t].z); da[3]=to_tf32(ra[t].w);
        float* db = Bs + wb*TILE + (rr + t*32)*LDK + kq*4;
        db[0]=to_tf32(rb[t].x); db[1]=to_tf32(rb[t].y); db[2]=to_tf32(rb[t].z); db[3]=to_tf32(rb[t].w);
      }
      __syncthreads();
    }
  }

  // fused epilogue: silu(gate)*up*router_weight -> g_act
  const int g = lane >> 2, c2 = (lane & 3)*2;
  #pragma unroll
  for (int mi=0;mi<2;mi++){
    #pragma unroll
    for (int hh=0; hh<2; hh++){
      int r = mw*32 + mi*16 + g + hh*8;
      int p = row0 + r;
      if (p < pend){
        float wgt = g_pw[p];
        float* arow = g_act + (size_t)p*ID + i0 + nw*32;
        #pragma unroll
        for (int ni=0;ni<4;ni++){
          #pragma unroll
          for (int j=0;j<2;j++){
            float gv = accg[mi][ni][hh*2+j];
            float uv = accu[mi][ni][hh*2+j];
            float sv = gv / (1.f + expf(-gv));
            arow[ni*8 + c2 + j] = wgt * sv * uv;
          }
        }
      }
    }
  }
}

// GEMM2: out[token, h0..h0+127] += act_p . down[e][h] (atomic scatter over K=8)
__global__ void gemm2_kernel(const float* __restrict__ DW, float* __restrict__ out)
{
  int mt = blockIdx.x;
  if (mt >= g_nmt) return;
  const int e = g_mt_e[mt], row0 = g_mt_r[mt], pend = g_off[e+1];
  const int h0 = blockIdx.y * 128;
  extern __shared__ float sm[];
  float* As = sm;
  float* Bs = sm + 2*TILE;

  const int tid = threadIdx.x, lane = tid & 31, wid = tid >> 5;
  const int mw = wid >> 1, nw = wid & 1;     // warp tile: 32m x 64n
  const int kq = tid & 7, rr = tid >> 3;

  const float* aptr[4];
  const float* bptr[4];
  {
    const float* dw_e = DW + (size_t)e * HD * ID;
    #pragma unroll
    for (int t=0;t<4;t++){
      int m = rr + t*32;
      int p = row0 + m;
      int pc = (p < pend) ? p : row0;
      aptr[t] = g_act + (size_t)pc*ID + kq*4;
      bptr[t] = dw_e + (size_t)(h0 + m)*ID + kq*4;
    }
  }

  float acc[2][8][4];
  #pragma unroll
  for (int a=0;a<2;a++)
    #pragma unroll
    for (int b=0;b<8;b++)
      #pragma unroll
      for (int q=0;q<4;q++) acc[a][b][q]=0.f;

  float4 ra[4], rb[4];
  #pragma unroll
  for (int t=0;t<4;t++){ ra[t] = *(const float4*)aptr[t]; rb[t] = *(const float4*)bptr[t]; }
  #pragma unroll
  for (int t=0;t<4;t++){
    float* da = As + (rr + t*32)*LDK + kq*4;
    da[0]=to_tf32(ra[t].x); da[1]=to_tf32(ra[t].y); da[2]=to_tf32(ra[t].z); da[3]=to_tf32(ra[t].w);
    float* db = Bs + (rr + t*32)*LDK + kq*4;
    db[0]=to_tf32(rb[t].x); db[1]=to_tf32(rb[t].y); db[2]=to_tf32(rb[t].z); db[3]=to_tf32(rb[t].w);
  }
  __syncthreads();

  const int NKT = ID / BK;   // 48
  for (int kt = 0; kt < NKT; kt++){
    const int cb = kt & 1;
    if (kt + 1 < NKT){
      const int ko = (kt+1)*BK;
      #pragma unroll
      for (int t=0;t<4;t++){ ra[t] = *(const float4*)(aptr[t]+ko); rb[t] = *(const float4*)(bptr[t]+ko); }
    }
    {
      const float* Ab = As + cb*TILE + (mw*32)*LDK;
      const float* Bb = Bs + cb*TILE + (nw*64)*LDK;
      const int g = lane >> 2, c = lane & 3;
      #pragma unroll
      for (int ks = 0; ks < 4; ks++){
        const int k0 = ks*8 + c;
        float a[2][4];
        #pragma unroll
        for (int mi=0;mi<2;mi++){
          const float* ap = Ab + (mi*16 + g)*LDK + k0;
          a[mi][0] = ap[0];       a[mi][2] = ap[4];
          a[mi][1] = ap[8*LDK];   a[mi][3] = ap[8*LDK+4];
        }
        #pragma unroll
        for (int ni=0;ni<8;ni++){
          const float* bp = Bb + (ni*8 + g)*LDK + k0;
          float b2[2] = { bp[0], bp[4] };
          mma_tf32(acc[0][ni], a[0], b2);
          mma_tf32(acc[1][ni], a[1], b2);
        }
      }
    }
    if (kt + 1 < NKT){
      const int wb = 1 - cb;
      #pragma unroll
      for (int t=0;t<4;t++){
        float* da = As + wb*TILE + (rr + t*32)*LDK + kq*4;
        da[0]=to_tf32(ra[t].x); da[1]=to_tf32(ra[t].y); da[2]=to_tf32(ra[t].z); da[3]=to_tf32(ra[t].w);
        float* db = Bs + wb*TILE + (rr + t*32)*LDK + kq*4;
        db[0]=to_tf32(rb[t].x); db[1]=to_tf32(rb[t].y); db[2]=to_tf32(rb[t].z); db[3]=to_tf32(rb[t].w);
      }
      __syncthreads();
    }
  }

  // epilogue: atomic scatter-add into out[token, h]
  const int g = lane >> 2, c2 = (lane & 3)*2;
  #pragma unroll
  for (int mi=0;mi<2;mi++){
    #pragma unroll
    for (int hh=0; hh<2; hh++){
      int r = mw*32 + mi*16 + g + hh*8;
      int p = row0 + r;
      if (p < pend){
        int tok = g_perm[p];
        float* orow = out + (size_t)tok*HD + h0 + nw*64;
        #pragma unroll
        for (int ni=0;ni<8;ni++){
          #pragma unroll
          for (int j=0;j<2;j++){
            atomicAdd(&orow[ni*8 + c2 + j], acc[mi][ni][hh*2+j]);
          }
        }
      }
    }
  }
}

// ---------------- launch ----------------------------------------------------
extern "C" void kernel_launch(void* const* d_in, const int* in_sizes, int n_in,
                              void* d_out, int out_size)
{
  const float* X  = (const float*)d_in[0];   // hidden_states [T, H]
  const int*   ix = (const int*)d_in[1];     // top_k_index   [T, K]
  const float* tw = (const float*)d_in[2];   // top_k_weights [T, K]
  const float* GU = (const float*)d_in[3];   // gate_up_proj  [E, 2I, H]
  const float* DW = (const float*)d_in[4];   // down_proj     [E, H, I]
  float* out = (float*)d_out;                // [T, H] fp32
  (void)in_sizes; (void)n_in; (void)out_size;

  cudaFuncSetAttribute(gemm1_kernel, cudaFuncAttributeMaxDynamicSharedMemorySize, SMEMB);
  cudaFuncSetAttribute(gemm2_kernel, cudaFuncAttributeMaxDynamicSharedMemorySize, SMEMB);

  zero_out_kernel<<<(NTOK*HD + 255)/256, 256>>>(out);
  route_kernel<<<1, 256>>>(ix, tw);
  gemm1_kernel<<<dim3(MAXMT, ID/64),  256, SMEMB>>>(X, GU);
  gemm2_kernel<<<dim3(MAXMT, HD/128), 256, SMEMB>>>(DW, out);
}